// round 13
// baseline (speedup 1.0000x reference)
#include <cuda_runtime.h>
#include <cstdint>

// Problem shape (fixed by reference)
#define T_DIM 16384
#define B_DIM 64
#define E_DIM 4096

#define TILE_ROWS 16
#define NTILES    (T_DIM / TILE_ROWS)   // 1024
#define THREADS   256
#define GRID      296                   // 2 blocks/SM x 148 SMs, all resident

// ---------------------------------------------------------------------------
// Decoupled-lookback state. NEVER reset: flags are epoch-encoded.
// epoch e: flag 2e+1 = aggregate published, 2e+2 = inclusive prefix published.
// Exactly GRID atomicAdd's per launch -> epoch = ticket / GRID is uniform
// across the launch and monotone across graph replays (deterministic).
// ---------------------------------------------------------------------------
__device__ int g_ticket;                              // monotone across replays
__device__ volatile int g_flag[NTILES];               // zero-init
__device__ volatile unsigned long long g_agg[NTILES];
__device__ volatile unsigned long long g_pref[NTILES];

__device__ __forceinline__ unsigned long long pack2(float a, float b) {
    return ((unsigned long long)__float_as_uint(b) << 32) | (unsigned long long)__float_as_uint(a);
}
__device__ __forceinline__ float2 unpack2(unsigned long long v) {
    return make_float2(__uint_as_float((unsigned)v), __uint_as_float((unsigned)(v >> 32)));
}

// ---------------------------------------------------------------------------
// Persistent fused kernel with software pipelining:
//   per iteration: reduce current tile -> scan + warp-parallel lookback
//   -> ISSUE next tile's gathers -> store current tile (hides gather latency)
// Compose (ordered): compose(earlier=(A,B), later=(a,b)) = (a*A, a*B + b)
// ---------------------------------------------------------------------------
__global__ void __launch_bounds__(THREADS) fused_kernel(
        const int* __restrict__ indices, const float* __restrict__ params,
        const float* __restrict__ M_prev, float* __restrict__ out) {
    __shared__ float2 s_ab[TILE_ROWS];     // per-row (alpha, beta)
    __shared__ float2 s_rowAB[TILE_ROWS];  // per-row scanned (A, B)
    __shared__ int s_epoch;

    const int tid  = threadIdx.x;
    const int lane = tid & 31;
    const int wid  = tid >> 5;
    const int r0   = wid * 2;              // this warp's rows within a tile

    if (tid == 0) {
        int ticket = atomicAdd(&g_ticket, 1);
        s_epoch = ticket / GRID;
    }

    // M_prev resident in registers: E/4 = 1024 float4, 256 threads -> 4 each
    const float4* M4 = (const float4*)M_prev;
    float4 m0 = __ldg(&M4[tid]);
    float4 m1 = __ldg(&M4[256 + tid]);
    float4 m2 = __ldg(&M4[512 + tid]);
    float4 m3 = __ldg(&M4[768 + tid]);

    __syncthreads();
    const int agg_lo = 2 * s_epoch + 1;    // flag value: aggregate ready

    const float2* p2 = (const float2*)params;

    // ---- prefetch gathers for this block's FIRST tile --------------------
    int tile = blockIdx.x;
    float2 a0, b0, a1, b1;                 // pipelined gather results
    {
        int2 i0 = ((const int2*)(indices + (size_t)(tile * TILE_ROWS + r0)     * B_DIM))[lane];
        int2 i1 = ((const int2*)(indices + (size_t)(tile * TILE_ROWS + r0 + 1) * B_DIM))[lane];
        a0 = __ldg(&p2[i0.x]);  b0 = __ldg(&p2[i0.y]);
        a1 = __ldg(&p2[i1.x]);  b1 = __ldg(&p2[i1.y]);
    }

    while (tile < NTILES) {
        const int t0   = tile * TILE_ROWS;
        const int next = tile + GRID;

        // ---- Phase A: reduce the prefetched gathers (rows r0, r0+1) ------
        {
            float s0a = a0.x + b0.x, s0b = a0.y + b0.y;
            float s1a = a1.x + b1.x, s1b = a1.y + b1.y;
            #pragma unroll
            for (int off = 16; off > 0; off >>= 1) {
                s0a += __shfl_xor_sync(0xFFFFFFFFu, s0a, off);
                s0b += __shfl_xor_sync(0xFFFFFFFFu, s0b, off);
                s1a += __shfl_xor_sync(0xFFFFFFFFu, s1a, off);
                s1b += __shfl_xor_sync(0xFFFFFFFFu, s1b, off);
            }
            if (lane == 0) {
                s_ab[r0]     = make_float2(s0a, s0b);
                s_ab[r0 + 1] = make_float2(s1a, s1b);
            }
        }
        __syncthreads();

        // ---- Phase B: 16-lane tile scan + warp-parallel lookback (warp 0)
        if (wid == 0) {
            float wa = 1.0f, wb = 0.0f;
            if (lane < TILE_ROWS) { wa = s_ab[lane].x; wb = s_ab[lane].y; }
            #pragma unroll
            for (int off = 1; off < TILE_ROWS; off <<= 1) {
                float pa = __shfl_up_sync(0xFFFFFFFFu, wa, off);
                float pb = __shfl_up_sync(0xFFFFFFFFu, wb, off);
                float na = (lane >= off) ? wa * pa          : wa;
                float nb = (lane >= off) ? fmaf(wa, pb, wb) : wb;
                wa = na; wb = nb;
            }
            float aga = __shfl_sync(0xFFFFFFFFu, wa, TILE_ROWS - 1);
            float agb = __shfl_sync(0xFFFFFFFFu, wb, TILE_ROWS - 1);

            if (lane == 0) {                 // publish aggregate ASAP
                g_agg[tile] = pack2(aga, agb);
                __threadfence();
                g_flag[tile] = agg_lo;
            }

            // warp-parallel lookback: 32 predecessors per window step
            float ea = 1.0f, eb = 0.0f;
            if (tile > 0) {
                float acc_a = 1.0f, acc_b = 0.0f;
                int base_hi = tile - 1;
                for (;;) {
                    int j = base_hi - 31 + lane;   // lane ascending == j ascending
                    bool valid = (j >= 0);
                    int f = 0;
                    if (valid) {
                        f = g_flag[j];
                        while (f < agg_lo) { __nanosleep(40); f = g_flag[j]; }
                    }
                    __threadfence();
                    unsigned mask2 = __ballot_sync(0xFFFFFFFFu, valid && (f > agg_lo));
                    int lead = mask2 ? (31 - __clz(mask2)) : -1;

                    float va = 1.0f, vb = 0.0f;
                    if (valid && lane >= lead) {
                        unsigned long long payload = (lane == lead) ? g_pref[j] : g_agg[j];
                        float2 p = unpack2(payload);
                        va = p.x; vb = p.y;
                    }
                    #pragma unroll
                    for (int off = 1; off < 32; off <<= 1) {
                        float pa = __shfl_up_sync(0xFFFFFFFFu, va, off);
                        float pb = __shfl_up_sync(0xFFFFFFFFu, vb, off);
                        float na = (lane >= off) ? va * pa          : va;
                        float nb = (lane >= off) ? fmaf(va, pb, vb) : vb;
                        va = na; vb = nb;
                    }
                    float cwa = __shfl_sync(0xFFFFFFFFu, va, 31);
                    float cwb = __shfl_sync(0xFFFFFFFFu, vb, 31);

                    if (lead >= 0) {
                        ea = acc_a * cwa;
                        eb = fmaf(acc_a, cwb, acc_b);
                        break;
                    }
                    float na = acc_a * cwa;
                    float nb = fmaf(acc_a, cwb, acc_b);
                    acc_a = na; acc_b = nb;
                    base_hi -= 32;
                    if (base_hi < 0) { ea = acc_a; eb = acc_b; break; }
                }
            }

            if (lane == 0) {                 // publish inclusive prefix
                g_pref[tile] = pack2(aga * ea, fmaf(aga, eb, agb));
                __threadfence();
                g_flag[tile] = agg_lo + 1;
            }
            if (lane < TILE_ROWS) {
                s_rowAB[lane] = make_float2(wa * ea, fmaf(wa, eb, wb));
            }
        }

        // ---- Pipeline: issue NEXT tile's gathers before the store burst --
        if (next < NTILES) {
            int2 i0 = ((const int2*)(indices + (size_t)(next * TILE_ROWS + r0)     * B_DIM))[lane];
            int2 i1 = ((const int2*)(indices + (size_t)(next * TILE_ROWS + r0 + 1) * B_DIM))[lane];
            a0 = __ldg(&p2[i0.x]);  b0 = __ldg(&p2[i0.y]);
            a1 = __ldg(&p2[i1.x]);  b1 = __ldg(&p2[i1.y]);
        }
        __syncthreads();

        // ---- Phase C: store 16 rows x 4096 (64 STG.128/thread) -----------
        float4* o4 = (float4*)out + (size_t)t0 * (E_DIM / 4);
        #pragma unroll
        for (int r = 0; r < TILE_ROWS; r++) {
            float a = s_rowAB[r].x;
            float b = s_rowAB[r].y;
            float4 v0, v1, v2, v3;
            v0.x = fmaf(a, m0.x, b); v0.y = fmaf(a, m0.y, b); v0.z = fmaf(a, m0.z, b); v0.w = fmaf(a, m0.w, b);
            v1.x = fmaf(a, m1.x, b); v1.y = fmaf(a, m1.y, b); v1.z = fmaf(a, m1.z, b); v1.w = fmaf(a, m1.w, b);
            v2.x = fmaf(a, m2.x, b); v2.y = fmaf(a, m2.y, b); v2.z = fmaf(a, m2.z, b); v2.w = fmaf(a, m2.w, b);
            v3.x = fmaf(a, m3.x, b); v3.y = fmaf(a, m3.y, b); v3.z = fmaf(a, m3.z, b); v3.w = fmaf(a, m3.w, b);
            float4* row = o4 + (size_t)r * (E_DIM / 4);
            __stcs(row + tid,       v0);
            __stcs(row + 256 + tid, v1);
            __stcs(row + 512 + tid, v2);
            __stcs(row + 768 + tid, v3);
        }
        __syncthreads();   // s_rowAB/s_ab safe to overwrite next iteration

        tile = next;
    }
}

// ---------------------------------------------------------------------------
extern "C" void kernel_launch(void* const* d_in, const int* in_sizes, int n_in,
                              void* d_out, int out_size) {
    const int*   indices = (const int*)d_in[0];   // (T, B) int32 (JAX downcast)
    const float* M_prev  = (const float*)d_in[1]; // (E,)   f32
    const float* params  = (const float*)d_in[2]; // (N, 2) f32
    float*       out     = (float*)d_out;         // (T, E) f32

    fused_kernel<<<GRID, THREADS>>>(indices, params, M_prev, out);
}

// round 14
// speedup vs baseline: 1.3889x; 1.3889x over previous
#include <cuda_runtime.h>
#include <cstdint>

// Problem shape (fixed by reference)
#define T_DIM 16384
#define B_DIM 64
#define E_DIM 4096

// Permuted scratch layout so the single-block scan kernel is fully coalesced:
//   P(t) = (t & 15) * 1024 + (t >> 4)
// Scan thread `tid` owns t = 16*tid + i (i=0..15) -> permuted addr i*1024+tid
// -> every warp access is one coalesced transaction.
__device__ __forceinline__ int PERM(int t) { return ((t & 15) << 10) | (t >> 4); }

// Scratch (allocation-free). Packed float2: (.x=alpha/A, .y=beta/B)
__device__ float2 g_ab[T_DIM];
__device__ float2 g_AB[T_DIM];

// ---------------------------------------------------------------------------
// Kernel 1: per-t gather + reduce over B=64.
// At the L1tex wavefront floor for ~1M random 8B gathers (~9.6us,
// occupancy-invariant, verified R6/R7/R8/R9). 2 rows/warp, 512-thr blocks.
// ---------------------------------------------------------------------------
#define K1_ROWS 2
__global__ void __launch_bounds__(512) gather_reduce_kernel(
        const int* __restrict__ indices, const float* __restrict__ params) {
    int gwarp = (blockIdx.x * blockDim.x + threadIdx.x) >> 5;
    int lane  = threadIdx.x & 31;
    int t0 = gwarp * K1_ROWS;

    const float2* p2 = (const float2*)params;

    int2 idx[K1_ROWS];
    #pragma unroll
    for (int r = 0; r < K1_ROWS; r++) {
        idx[r] = ((const int2*)(indices + (size_t)(t0 + r) * B_DIM))[lane];
    }

    float2 v0[K1_ROWS], v1[K1_ROWS];
    #pragma unroll
    for (int r = 0; r < K1_ROWS; r++) v0[r] = __ldg(&p2[idx[r].x]);
    #pragma unroll
    for (int r = 0; r < K1_ROWS; r++) v1[r] = __ldg(&p2[idx[r].y]);

    #pragma unroll
    for (int r = 0; r < K1_ROWS; r++) {
        float sa = v0[r].x + v1[r].x;
        float sb = v0[r].y + v1[r].y;
        #pragma unroll
        for (int off = 16; off > 0; off >>= 1) {
            sa += __shfl_xor_sync(0xFFFFFFFFu, sa, off);
            sb += __shfl_xor_sync(0xFFFFFFFFu, sb, off);
        }
        if (lane == 0) {
            g_ab[PERM(t0 + r)] = make_float2(sa, sb);
        }
    }
}

// ---------------------------------------------------------------------------
// Kernel 2: linear-recurrence scan over T=16384.
// Single block, 1024 threads, 16 elements/thread, shuffle-based block scan.
// Compose (ordered): compose(earlier=(A,B), later=(a,b)) = (a*A, a*B + b)
// ---------------------------------------------------------------------------
__global__ void __launch_bounds__(1024) scan_kernel() {
    __shared__ float2 sW[32];   // per-warp inclusive totals

    const int tid  = threadIdx.x;
    const int lane = tid & 31;
    const int wid  = tid >> 5;

    float2 e[16];
    #pragma unroll
    for (int i = 0; i < 16; i++) e[i] = g_ab[i * 1024 + tid];

    // thread-local inclusive aggregate (in order)
    float ca = 1.0f, cb = 0.0f;
    #pragma unroll
    for (int i = 0; i < 16; i++) {
        cb = fmaf(e[i].x, cb, e[i].y);
        ca = e[i].x * ca;
    }

    // warp inclusive scan over thread aggregates:
    // new = compose(prev_from_lower=(pa,pb), mine=(wa,wb)) = (wa*pa, wa*pb+wb)
    float wa = ca, wb = cb;
    #pragma unroll
    for (int off = 1; off < 32; off <<= 1) {
        float pa = __shfl_up_sync(0xFFFFFFFFu, wa, off);
        float pb = __shfl_up_sync(0xFFFFFFFFu, wb, off);
        float na = (lane >= off) ? wa * pa          : wa;
        float nb = (lane >= off) ? fmaf(wa, pb, wb) : wb;
        wa = na; wb = nb;
    }

    if (lane == 31) sW[wid] = make_float2(wa, wb);
    __syncthreads();

    // warp 0 scans the 32 warp totals (inclusive)
    if (wid == 0) {
        float xa = sW[lane].x, xb = sW[lane].y;
        #pragma unroll
        for (int off = 1; off < 32; off <<= 1) {
            float pa = __shfl_up_sync(0xFFFFFFFFu, xa, off);
            float pb = __shfl_up_sync(0xFFFFFFFFu, xb, off);
            float na = (lane >= off) ? xa * pa          : xa;
            float nb = (lane >= off) ? fmaf(xa, pb, xb) : xb;
            xa = na; xb = nb;
        }
        sW[lane] = make_float2(xa, xb);
    }
    __syncthreads();

    // block-exclusive prefix = compose(warp_prefix, lane_exclusive)
    float wpa = (wid > 0) ? sW[wid - 1].x : 1.0f;
    float wpb = (wid > 0) ? sW[wid - 1].y : 0.0f;
    float lea = __shfl_up_sync(0xFFFFFFFFu, wa, 1);
    float leb = __shfl_up_sync(0xFFFFFFFFu, wb, 1);
    if (lane == 0) { lea = 1.0f; leb = 0.0f; }
    float pa = lea * wpa;
    float pb = fmaf(lea, wpb, leb);

    // replay local elements applying prefix; coalesced permuted writes
    #pragma unroll
    for (int i = 0; i < 16; i++) {
        pb = fmaf(e[i].x, pb, e[i].y);
        pa = e[i].x * pa;
        g_AB[i * 1024 + tid] = make_float2(pa, pb);
    }
}

// ---------------------------------------------------------------------------
// Kernel 3: output broadcast.  out[t, e] = A[t] * M_prev[e] + B[t]
// Block = one E-chunk (1024 floats as float4) x 16 t-rows; A/B staged to
// shared; 16 independent STG.128 streams/thread with __stcs (write-once
// output, 2x L2 capacity). Measured at ~6.9 TB/s — the HBM write ceiling.
// ---------------------------------------------------------------------------
#define K3_ROWS   16
#define K3_CHUNKS (E_DIM / (256 * 4))   // 4 column chunks of 1024 floats

__global__ void __launch_bounds__(256) broadcast_kernel(
        const float* __restrict__ M_prev, float* __restrict__ out) {
    __shared__ float2 sAB[K3_ROWS];

    const int t0  = blockIdx.y * K3_ROWS;   // multiple of 16
    const int grp = t0 >> 4;                // PERM(t0+r) = r*1024 + grp
    if (threadIdx.x < K3_ROWS) {
        sAB[threadIdx.x] = g_AB[threadIdx.x * 1024 + grp];
    }

    const int col = blockIdx.x * 256 + threadIdx.x;   // float4 column index
    float4 m = __ldg(&((const float4*)M_prev)[col]);
    __syncthreads();

    float4* o4 = (float4*)out;
    #pragma unroll
    for (int r = 0; r < K3_ROWS; r++) {
        float a = sAB[r].x;
        float b = sAB[r].y;
        float4 v;
        v.x = fmaf(a, m.x, b);
        v.y = fmaf(a, m.y, b);
        v.z = fmaf(a, m.z, b);
        v.w = fmaf(a, m.w, b);
        __stcs(&o4[(size_t)(t0 + r) * (E_DIM / 4) + col], v);
    }
}

// ---------------------------------------------------------------------------
extern "C" void kernel_launch(void* const* d_in, const int* in_sizes, int n_in,
                              void* d_out, int out_size) {
    const int*   indices = (const int*)d_in[0];   // (T, B) int32 (JAX downcast)
    const float* M_prev  = (const float*)d_in[1]; // (E,)   f32
    const float* params  = (const float*)d_in[2]; // (N, 2) f32
    float*       out     = (float*)d_out;         // (T, E) f32

    // K1: 8192 warps (2 rows each), 512-thread blocks
    gather_reduce_kernel<<<T_DIM / K1_ROWS * 32 / 512, 512>>>(indices, params);

    // K2: single-block shuffle scan
    scan_kernel<<<1, 1024>>>();

    // K3: (4 column chunks) x (1024 row groups)
    dim3 g3(K3_CHUNKS, T_DIM / K3_ROWS);
    broadcast_kernel<<<g3, 256>>>(M_prev, out);
}